// round 1
// baseline (speedup 1.0000x reference)
#include <cuda_runtime.h>
#include <cstdint>

#define BH_NUM 64
#define S_LEN  2048
#define DHEAD  64

// round-to-nearest tf32 conversion (keeps bit pattern in a b32 reg)
__device__ __forceinline__ unsigned f2tf32(float x){
    unsigned r;
    asm("cvt.rna.tf32.f32 %0, %1;" : "=r"(r) : "f"(x));
    return r;
}

// D = A*B + D,  m16n8k8 tf32, fp32 accumulate
__device__ __forceinline__ void mma_tf32(float c[4], const unsigned a[4],
                                         unsigned b0, unsigned b1){
    asm volatile(
        "mma.sync.aligned.m16n8k8.row.col.f32.tf32.tf32.f32 "
        "{%0,%1,%2,%3}, {%4,%5,%6,%7}, {%8,%9}, {%0,%1,%2,%3};\n"
        : "+f"(c[0]), "+f"(c[1]), "+f"(c[2]), "+f"(c[3])
        : "r"(a[0]), "r"(a[1]), "r"(a[2]), "r"(a[3]), "r"(b0), "r"(b1));
}

// Flash attention: CTA = 64 q-rows (4 warps x 16 rows), KV tiles of 64 keys.
// Smem swizzles (all verified conflict-free for the fragment access patterns):
//   Q/K/P tile: element (r,c) stored at r*64 + (c ^ ((r&7)<<2))
//   V tile:     element (r,c) stored at r*64 + (c ^ ((r&3)<<3))
__global__ void __launch_bounds__(128, 3)
sdpa_flash_tf32(const float* __restrict__ Qg, const float* __restrict__ Kg,
                const float* __restrict__ Vg, float* __restrict__ Og)
{
    __shared__ unsigned Ks[64*64];   // K tile (also Q staging)
    __shared__ unsigned Vs[64*64];   // V tile
    __shared__ unsigned Ps[64*64];   // P, 16 rows per warp

    const int tid  = threadIdx.x;
    const int w    = tid >> 5;
    const int lane = tid & 31;
    const int qg   = lane >> 2;      // 0..7  (groupID)
    const int rg   = lane & 3;       // 0..3  (threadID-in-group)
    const int swzA = qg << 2;
    const int swzB = rg << 3;

    const int qt = blockIdx.x;       // 0..31  q tile
    const int bh = blockIdx.y;       // 0..63  batch*head

    const size_t base = (size_t)bh * S_LEN * DHEAD;

    // ---- stage Q tile (scale 1/sqrt(64) folded in, tf32-rounded) ----
    {
        const float4* Qt4 = (const float4*)(Qg + base + (size_t)qt*64*DHEAD);
        #pragma unroll
        for (int i = 0; i < 8; i++){
            int idx = tid + i*128;           // float4 index 0..1023
            int row = idx >> 4;
            int c4  = (idx & 15) << 2;
            float4 v = Qt4[idx];
            int d = row*64 + (c4 ^ ((row & 7) << 2));
            Ks[d+0] = f2tf32(v.x * 0.125f);
            Ks[d+1] = f2tf32(v.y * 0.125f);
            Ks[d+2] = f2tf32(v.z * 0.125f);
            Ks[d+3] = f2tf32(v.w * 0.125f);
        }
    }
    __syncthreads();

    // Q fragments held in registers for the whole kernel (8 k-chunks x 4 regs)
    unsigned qa[8][4];
    {
        const int r0 = w*16 + qg;
        #pragma unroll
        for (int kc = 0; kc < 8; kc++){
            int c0 = (kc*8 + rg) ^ swzA;
            qa[kc][0] = Ks[ r0     *64 +  c0   ];
            qa[kc][1] = Ks[(r0+8)  *64 +  c0   ];
            qa[kc][2] = Ks[ r0     *64 + (c0^4)];
            qa[kc][3] = Ks[(r0+8)  *64 + (c0^4)];
        }
    }
    __syncthreads();   // done with Q staging; Ks now free for K tiles

    float o[8][4];
    #pragma unroll
    for (int j = 0; j < 8; j++){ o[j][0]=0.f; o[j][1]=0.f; o[j][2]=0.f; o[j][3]=0.f; }
    float m0 = -1e30f, m1 = -1e30f, l0 = 0.f, l1 = 0.f;

    unsigned* Pw = Ps + w*(16*64);   // per-warp P region (rows 0..15)

    for (int kt = 0; kt < S_LEN/64; kt++){
        // ---- load K & V tiles (contiguous 16KB each), tf32-rounded, swizzled ----
        const float4* Kt4 = (const float4*)(Kg + base + (size_t)kt*64*DHEAD);
        const float4* Vt4 = (const float4*)(Vg + base + (size_t)kt*64*DHEAD);
        #pragma unroll
        for (int i = 0; i < 8; i++){
            int idx = tid + i*128;
            int row = idx >> 4;
            int c4  = (idx & 15) << 2;
            float4 kv = Kt4[idx];
            int dk = row*64 + (c4 ^ ((row & 7) << 2));
            Ks[dk+0]=f2tf32(kv.x); Ks[dk+1]=f2tf32(kv.y);
            Ks[dk+2]=f2tf32(kv.z); Ks[dk+3]=f2tf32(kv.w);
            float4 vv = Vt4[idx];
            int dv = row*64 + (c4 ^ ((row & 3) << 3));
            Vs[dv+0]=f2tf32(vv.x); Vs[dv+1]=f2tf32(vv.y);
            Vs[dv+2]=f2tf32(vv.z); Vs[dv+3]=f2tf32(vv.w);
        }
        __syncthreads();

        // ---- S = Q K^T  (warp: 16 rows x 64 keys) ----
        float sc[8][4];
        #pragma unroll
        for (int j = 0; j < 8; j++){ sc[j][0]=0.f; sc[j][1]=0.f; sc[j][2]=0.f; sc[j][3]=0.f; }
        #pragma unroll
        for (int kc = 0; kc < 8; kc++){
            int c0 = (kc*8 + rg) ^ swzA;
            #pragma unroll
            for (int j = 0; j < 8; j++){
                int rowb = (j*8 + qg)*64;         // (key&7)==qg -> swizzle == swzA
                unsigned b0 = Ks[rowb +  c0   ];
                unsigned b1 = Ks[rowb + (c0^4)];
                mma_tf32(sc[j], qa[kc], b0, b1);
            }
        }

        // ---- online softmax (rows r=qg and r+8; quad = lanes sharing qg) ----
        float tm0 = -1e30f, tm1 = -1e30f;
        #pragma unroll
        for (int j = 0; j < 8; j++){
            tm0 = fmaxf(tm0, fmaxf(sc[j][0], sc[j][1]));
            tm1 = fmaxf(tm1, fmaxf(sc[j][2], sc[j][3]));
        }
        tm0 = fmaxf(tm0, __shfl_xor_sync(0xffffffffu, tm0, 1));
        tm0 = fmaxf(tm0, __shfl_xor_sync(0xffffffffu, tm0, 2));
        tm1 = fmaxf(tm1, __shfl_xor_sync(0xffffffffu, tm1, 1));
        tm1 = fmaxf(tm1, __shfl_xor_sync(0xffffffffu, tm1, 2));
        float nm0 = fmaxf(m0, tm0), nm1 = fmaxf(m1, tm1);
        float al0 = __expf(m0 - nm0), al1 = __expf(m1 - nm1);
        m0 = nm0; m1 = nm1;

        float rs0 = 0.f, rs1 = 0.f;
        #pragma unroll
        for (int j = 0; j < 8; j++){
            float p0 = __expf(sc[j][0] - nm0);
            float p1 = __expf(sc[j][1] - nm0);
            float p2 = __expf(sc[j][2] - nm1);
            float p3 = __expf(sc[j][3] - nm1);
            rs0 += p0 + p1;  rs1 += p2 + p3;
            int c = (j*8 + 2*rg) ^ swzA;              // row&7 == qg for both halves
            *(uint2*)&Pw[ qg   *64 + c] = make_uint2(f2tf32(p0), f2tf32(p1));
            *(uint2*)&Pw[(qg+8)*64 + c] = make_uint2(f2tf32(p2), f2tf32(p3));
            o[j][0]*=al0; o[j][1]*=al0; o[j][2]*=al1; o[j][3]*=al1;
        }
        rs0 += __shfl_xor_sync(0xffffffffu, rs0, 1);
        rs0 += __shfl_xor_sync(0xffffffffu, rs0, 2);
        rs1 += __shfl_xor_sync(0xffffffffu, rs1, 1);
        rs1 += __shfl_xor_sync(0xffffffffu, rs1, 2);
        l0 = l0*al0 + rs0;
        l1 = l1*al1 + rs1;

        __syncwarp();   // P visible within the warp

        // ---- O += P V  (k dim = 64 keys, n dim = 64 head-dims) ----
        #pragma unroll
        for (int kc = 0; kc < 8; kc++){
            unsigned a[4];
            int c0 = (kc*8 + rg) ^ swzA;
            a[0] = Pw[ qg   *64 +  c0   ];
            a[1] = Pw[(qg+8)*64 +  c0   ];
            a[2] = Pw[ qg   *64 + (c0^4)];
            a[3] = Pw[(qg+8)*64 + (c0^4)];
            int vrow = (kc*8 + rg)*64;                // (key&3)==rg -> swizzle == swzB
            #pragma unroll
            for (int j = 0; j < 8; j++){
                int cv = (j*8 + qg) ^ swzB;
                unsigned b0 = Vs[vrow +        cv];
                unsigned b1 = Vs[vrow + 256 +  cv];   // key+4 -> +4 rows, same swizzle
                mma_tf32(o[j], a, b0, b1);
            }
        }
        __syncthreads();   // protect Ks/Vs before next tile's fill
    }

    // ---- epilogue: O /= l, write fp32 ----
    float inv0 = 1.f / l0, inv1 = 1.f / l1;
    const int row0 = qt*64 + w*16 + qg;
    float2* Od = (float2*)(Og + base);
    #pragma unroll
    for (int j = 0; j < 8; j++){
        int d = j*8 + 2*rg;
        Od[( row0   *64 + d) >> 1] = make_float2(o[j][0]*inv0, o[j][1]*inv0);
        Od[((row0+8)*64 + d) >> 1] = make_float2(o[j][2]*inv1, o[j][3]*inv1);
    }
}

extern "C" void kernel_launch(void* const* d_in, const int* in_sizes, int n_in,
                              void* d_out, int out_size){
    const float* Q = (const float*)d_in[0];
    const float* K = (const float*)d_in[1];
    const float* V = (const float*)d_in[2];
    float* O = (float*)d_out;
    dim3 grid(S_LEN/64, BH_NUM);   // q-tile fastest -> same-bh CTAs concurrent -> K/V hit L2
    sdpa_flash_tf32<<<grid, 128>>>(Q, K, V, O);
}

// round 3
// speedup vs baseline: 1.0007x; 1.0007x over previous
#include <cuda_runtime.h>
#include <cstdint>

#define BH_NUM 64
#define S_LEN  2048
#define DHEAD  64

// round-to-nearest tf32 conversion (keeps bit pattern in a b32 reg)
__device__ __forceinline__ unsigned f2tf32(float x){
    unsigned r;
    asm("cvt.rna.tf32.f32 %0, %1;" : "=r"(r) : "f"(x));
    return r;
}

// D = A*B + D,  m16n8k8 tf32, fp32 accumulate
__device__ __forceinline__ void mma_tf32(float c[4], const unsigned a[4],
                                         unsigned b0, unsigned b1){
    asm volatile(
        "mma.sync.aligned.m16n8k8.row.col.f32.tf32.tf32.f32 "
        "{%0,%1,%2,%3}, {%4,%5,%6,%7}, {%8,%9}, {%0,%1,%2,%3};\n"
        : "+f"(c[0]), "+f"(c[1]), "+f"(c[2]), "+f"(c[3])
        : "r"(a[0]), "r"(a[1]), "r"(a[2]), "r"(a[3]), "r"(b0), "r"(b1));
}

// Flash attention: CTA = 64 q-rows (4 warps x 16 rows), KV tiles of 64 keys.
// Smem swizzles (all verified conflict-free for the fragment access patterns):
//   Q/K/P tile: element (r,c) stored at r*64 + (c ^ ((r&7)<<2))
//   V tile:     element (r,c) stored at r*64 + (c ^ ((r&3)<<3))
__global__ void __launch_bounds__(128, 3)
sdpa_flash_tf32(const float* __restrict__ Qg, const float* __restrict__ Kg,
                const float* __restrict__ Vg, float* __restrict__ Og)
{
    __shared__ unsigned Ks[64*64];   // K tile (also Q staging)
    __shared__ unsigned Vs[64*64];   // V tile
    __shared__ unsigned Ps[64*64];   // P, 16 rows per warp

    const int tid  = threadIdx.x;
    const int w    = tid >> 5;
    const int lane = tid & 31;
    const int qg   = lane >> 2;      // 0..7  (groupID)
    const int rg   = lane & 3;       // 0..3  (threadID-in-group)
    const int swzA = qg << 2;
    const int swzB = rg << 3;

    const int qt = blockIdx.x;       // 0..31  q tile
    const int bh = blockIdx.y;       // 0..63  batch*head

    const size_t base = (size_t)bh * S_LEN * DHEAD;

    // ---- stage Q tile (scale 1/sqrt(64) folded in, tf32-rounded) ----
    {
        const float4* Qt4 = (const float4*)(Qg + base + (size_t)qt*64*DHEAD);
        #pragma unroll
        for (int i = 0; i < 8; i++){
            int idx = tid + i*128;           // float4 index 0..1023
            int row = idx >> 4;
            int c4  = (idx & 15) << 2;
            float4 v = Qt4[idx];
            int d = row*64 + (c4 ^ ((row & 7) << 2));
            Ks[d+0] = f2tf32(v.x * 0.125f);
            Ks[d+1] = f2tf32(v.y * 0.125f);
            Ks[d+2] = f2tf32(v.z * 0.125f);
            Ks[d+3] = f2tf32(v.w * 0.125f);
        }
    }
    __syncthreads();

    // Q fragments held in registers for the whole kernel (8 k-chunks x 4 regs)
    unsigned qa[8][4];
    {
        const int r0 = w*16 + qg;
        #pragma unroll
        for (int kc = 0; kc < 8; kc++){
            int c0 = (kc*8 + rg) ^ swzA;
            qa[kc][0] = Ks[ r0     *64 +  c0   ];
            qa[kc][1] = Ks[(r0+8)  *64 +  c0   ];
            qa[kc][2] = Ks[ r0     *64 + (c0^4)];
            qa[kc][3] = Ks[(r0+8)  *64 + (c0^4)];
        }
    }
    __syncthreads();   // done with Q staging; Ks now free for K tiles

    float o[8][4];
    #pragma unroll
    for (int j = 0; j < 8; j++){ o[j][0]=0.f; o[j][1]=0.f; o[j][2]=0.f; o[j][3]=0.f; }
    float m0 = -1e30f, m1 = -1e30f, l0 = 0.f, l1 = 0.f;

    unsigned* Pw = Ps + w*(16*64);   // per-warp P region (rows 0..15)

    for (int kt = 0; kt < S_LEN/64; kt++){
        // ---- load K & V tiles (contiguous 16KB each), tf32-rounded, swizzled ----
        const float4* Kt4 = (const float4*)(Kg + base + (size_t)kt*64*DHEAD);
        const float4* Vt4 = (const float4*)(Vg + base + (size_t)kt*64*DHEAD);
        #pragma unroll
        for (int i = 0; i < 8; i++){
            int idx = tid + i*128;
            int row = idx >> 4;
            int c4  = (idx & 15) << 2;
            float4 kv = Kt4[idx];
            int dk = row*64 + (c4 ^ ((row & 7) << 2));
            Ks[dk+0]=f2tf32(kv.x); Ks[dk+1]=f2tf32(kv.y);
            Ks[dk+2]=f2tf32(kv.z); Ks[dk+3]=f2tf32(kv.w);
            float4 vv = Vt4[idx];
            int dv = row*64 + (c4 ^ ((row & 3) << 3));
            Vs[dv+0]=f2tf32(vv.x); Vs[dv+1]=f2tf32(vv.y);
            Vs[dv+2]=f2tf32(vv.z); Vs[dv+3]=f2tf32(vv.w);
        }
        __syncthreads();

        // ---- S = Q K^T  (warp: 16 rows x 64 keys) ----
        float sc[8][4];
        #pragma unroll
        for (int j = 0; j < 8; j++){ sc[j][0]=0.f; sc[j][1]=0.f; sc[j][2]=0.f; sc[j][3]=0.f; }
        #pragma unroll
        for (int kc = 0; kc < 8; kc++){
            int c0 = (kc*8 + rg) ^ swzA;
            #pragma unroll
            for (int j = 0; j < 8; j++){
                int rowb = (j*8 + qg)*64;         // (key&7)==qg -> swizzle == swzA
                unsigned b0 = Ks[rowb +  c0   ];
                unsigned b1 = Ks[rowb + (c0^4)];
                mma_tf32(sc[j], qa[kc], b0, b1);
            }
        }

        // ---- online softmax (rows r=qg and r+8; quad = lanes sharing qg) ----
        float tm0 = -1e30f, tm1 = -1e30f;
        #pragma unroll
        for (int j = 0; j < 8; j++){
            tm0 = fmaxf(tm0, fmaxf(sc[j][0], sc[j][1]));
            tm1 = fmaxf(tm1, fmaxf(sc[j][2], sc[j][3]));
        }
        tm0 = fmaxf(tm0, __shfl_xor_sync(0xffffffffu, tm0, 1));
        tm0 = fmaxf(tm0, __shfl_xor_sync(0xffffffffu, tm0, 2));
        tm1 = fmaxf(tm1, __shfl_xor_sync(0xffffffffu, tm1, 1));
        tm1 = fmaxf(tm1, __shfl_xor_sync(0xffffffffu, tm1, 2));
        float nm0 = fmaxf(m0, tm0), nm1 = fmaxf(m1, tm1);
        float al0 = __expf(m0 - nm0), al1 = __expf(m1 - nm1);
        m0 = nm0; m1 = nm1;

        float rs0 = 0.f, rs1 = 0.f;
        #pragma unroll
        for (int j = 0; j < 8; j++){
            float p0 = __expf(sc[j][0] - nm0);
            float p1 = __expf(sc[j][1] - nm0);
            float p2 = __expf(sc[j][2] - nm1);
            float p3 = __expf(sc[j][3] - nm1);
            rs0 += p0 + p1;  rs1 += p2 + p3;
            int c = (j*8 + 2*rg) ^ swzA;              // row&7 == qg for both halves
            *(uint2*)&Pw[ qg   *64 + c] = make_uint2(f2tf32(p0), f2tf32(p1));
            *(uint2*)&Pw[(qg+8)*64 + c] = make_uint2(f2tf32(p2), f2tf32(p3));
            o[j][0]*=al0; o[j][1]*=al0; o[j][2]*=al1; o[j][3]*=al1;
        }
        rs0 += __shfl_xor_sync(0xffffffffu, rs0, 1);
        rs0 += __shfl_xor_sync(0xffffffffu, rs0, 2);
        rs1 += __shfl_xor_sync(0xffffffffu, rs1, 1);
        rs1 += __shfl_xor_sync(0xffffffffu, rs1, 2);
        l0 = l0*al0 + rs0;
        l1 = l1*al1 + rs1;

        __syncwarp();   // P visible within the warp

        // ---- O += P V  (k dim = 64 keys, n dim = 64 head-dims) ----
        #pragma unroll
        for (int kc = 0; kc < 8; kc++){
            unsigned a[4];
            int c0 = (kc*8 + rg) ^ swzA;
            a[0] = Pw[ qg   *64 +  c0   ];
            a[1] = Pw[(qg+8)*64 +  c0   ];
            a[2] = Pw[ qg   *64 + (c0^4)];
            a[3] = Pw[(qg+8)*64 + (c0^4)];
            int vrow = (kc*8 + rg)*64;                // (key&3)==rg -> swizzle == swzB
            #pragma unroll
            for (int j = 0; j < 8; j++){
                int cv = (j*8 + qg) ^ swzB;
                unsigned b0 = Vs[vrow +        cv];
                unsigned b1 = Vs[vrow + 256 +  cv];   // key+4 -> +4 rows, same swizzle
                mma_tf32(o[j], a, b0, b1);
            }
        }
        __syncthreads();   // protect Ks/Vs before next tile's fill
    }

    // ---- epilogue: O /= l, write fp32 ----
    float inv0 = 1.f / l0, inv1 = 1.f / l1;
    const int row0 = qt*64 + w*16 + qg;
    float2* Od = (float2*)(Og + base);
    #pragma unroll
    for (int j = 0; j < 8; j++){
        int d = j*8 + 2*rg;
        Od[( row0   *64 + d) >> 1] = make_float2(o[j][0]*inv0, o[j][1]*inv0);
        Od[((row0+8)*64 + d) >> 1] = make_float2(o[j][2]*inv1, o[j][3]*inv1);
    }
}

extern "C" void kernel_launch(void* const* d_in, const int* in_sizes, int n_in,
                              void* d_out, int out_size){
    const float* Q = (const float*)d_in[0];
    const float* K = (const float*)d_in[1];
    const float* V = (const float*)d_in[2];
    float* O = (float*)d_out;
    dim3 grid(S_LEN/64, BH_NUM);   // q-tile fastest -> same-bh CTAs concurrent -> K/V hit L2
    sdpa_flash_tf32<<<grid, 128>>>(Q, K, V, O);
}

// round 5
// speedup vs baseline: 1.2932x; 1.2923x over previous
#include <cuda_runtime.h>
#include <cstdint>

#define BH_NUM 64
#define S_LEN  2048
#define DHEAD  64

// round-to-nearest tf32 conversion (keeps bit pattern in a b32 reg)
__device__ __forceinline__ unsigned f2tf32(float x){
    unsigned r;
    asm("cvt.rna.tf32.f32 %0, %1;" : "=r"(r) : "f"(x));
    return r;
}

// D = A*B + D,  m16n8k8 tf32, fp32 accumulate
__device__ __forceinline__ void mma_tf32(float c[4], const unsigned a[4],
                                         unsigned b0, unsigned b1){
    asm volatile(
        "mma.sync.aligned.m16n8k8.row.col.f32.tf32.tf32.f32 "
        "{%0,%1,%2,%3}, {%4,%5,%6,%7}, {%8,%9}, {%0,%1,%2,%3};\n"
        : "+f"(c[0]), "+f"(c[1]), "+f"(c[2]), "+f"(c[3])
        : "r"(a[0]), "r"(a[1]), "r"(a[2]), "r"(a[3]), "r"(b0), "r"(b1));
}

// Flash attention v4: CTA = 128 q-rows, 4 warps x 32 rows (2 row-tiles each).
// Each K/V B-fragment load feeds TWO mmas (both row-tiles) -> halves B smem traffic.
// Smem swizzles (verified conflict-free):
//   Q/K/P tile: element (r,c) at r*64 + (c ^ ((r&7)<<2))
//   V tile:     element (r,c) at r*64 + (c ^ ((r&3)<<3))
// P overwrites Ks after QK^T (all warps synced), so static smem = 48KB.
__global__ void __launch_bounds__(128, 2)
sdpa_flash_tf32_v4(const float* __restrict__ Qg, const float* __restrict__ Kg,
                   const float* __restrict__ Vg, float* __restrict__ Og)
{
    __shared__ unsigned Ks[64*64];    // K tile; reused as P rows for warps 0,1
    __shared__ unsigned Vs[64*64];    // V tile
    __shared__ unsigned Pext[64*64];  // P rows for warps 2,3

    const int tid  = threadIdx.x;
    const int w    = tid >> 5;
    const int lane = tid & 31;
    const int qg   = lane >> 2;      // 0..7
    const int rg   = lane & 3;       // 0..3
    const int swzA = qg << 2;
    const int swzB = rg << 3;

    const int qt = blockIdx.x;       // 0..15  q tile (128 rows)
    const int bh = blockIdx.y;       // 0..63

    const size_t base = (size_t)bh * S_LEN * DHEAD;

    // ---- stage Q tile (128x64): rows 0..63 in Ks, rows 64..127 in Vs ----
    {
        const float4* Qt4 = (const float4*)(Qg + base + (size_t)qt*128*DHEAD);
        #pragma unroll
        for (int i = 0; i < 16; i++){
            int idx = tid + i*128;           // float4 index 0..2047
            int row = idx >> 4;
            int c4  = (idx & 15) << 2;
            float4 v = Qt4[idx];
            unsigned* dst = (row < 64) ? Ks : Vs;
            int r = row & 63;
            int d = r*64 + (c4 ^ ((row & 7) << 2));   // row&7 == r&7
            dst[d+0] = f2tf32(v.x * 0.125f);
            dst[d+1] = f2tf32(v.y * 0.125f);
            dst[d+2] = f2tf32(v.z * 0.125f);
            dst[d+3] = f2tf32(v.w * 0.125f);
        }
    }
    __syncthreads();

    // Q fragments in registers for the whole kernel: 2 row-tiles x 8 k-chunks x 4
    unsigned qa[2][8][4];
    #pragma unroll
    for (int rt = 0; rt < 2; rt++){
        const int grow = w*32 + rt*16 + qg;          // global row in 0..127
        const unsigned* src = (grow < 64) ? Ks : Vs; // rows grow and grow+8 stay in same half (w*32+rt*16 multiple of 16)
        const int r0 = grow & 63;
        #pragma unroll
        for (int kc = 0; kc < 8; kc++){
            int c0 = (kc*8 + rg) ^ swzA;
            qa[rt][kc][0] = src[ r0    *64 +  c0   ];
            qa[rt][kc][1] = src[(r0+8) *64 +  c0   ];
            qa[rt][kc][2] = src[ r0    *64 + (c0^4)];
            qa[rt][kc][3] = src[(r0+8) *64 + (c0^4)];
        }
    }
    __syncthreads();   // Q staging done; Ks/Vs free

    float o[2][8][4];
    #pragma unroll
    for (int rt = 0; rt < 2; rt++)
        #pragma unroll
        for (int j = 0; j < 8; j++){
            o[rt][j][0]=0.f; o[rt][j][1]=0.f; o[rt][j][2]=0.f; o[rt][j][3]=0.f;
        }
    float m0[2] = {-1e30f,-1e30f}, m1[2] = {-1e30f,-1e30f};
    float l0[2] = {0.f,0.f},       l1[2] = {0.f,0.f};

    // per-warp P region (32 rows x 64): warps 0,1 -> Ks, warps 2,3 -> Pext
    unsigned* Pw = (w < 2) ? (Ks + w*2048) : (Pext + (w-2)*2048);

    for (int kt = 0; kt < S_LEN/64; kt++){
        // ---- fill K & V tiles, tf32-rounded, swizzled ----
        const float4* Kt4 = (const float4*)(Kg + base + (size_t)kt*64*DHEAD);
        const float4* Vt4 = (const float4*)(Vg + base + (size_t)kt*64*DHEAD);
        #pragma unroll
        for (int i = 0; i < 8; i++){
            int idx = tid + i*128;
            int row = idx >> 4;
            int c4  = (idx & 15) << 2;
            float4 kv = Kt4[idx];
            int dk = row*64 + (c4 ^ ((row & 7) << 2));
            Ks[dk+0]=f2tf32(kv.x); Ks[dk+1]=f2tf32(kv.y);
            Ks[dk+2]=f2tf32(kv.z); Ks[dk+3]=f2tf32(kv.w);
            float4 vv = Vt4[idx];
            int dv = row*64 + (c4 ^ ((row & 3) << 3));
            Vs[dv+0]=f2tf32(vv.x); Vs[dv+1]=f2tf32(vv.y);
            Vs[dv+2]=f2tf32(vv.z); Vs[dv+3]=f2tf32(vv.w);
        }
        __syncthreads();

        // ---- S = Q K^T : each B load feeds BOTH row-tiles ----
        float sc[2][8][4];
        #pragma unroll
        for (int rt = 0; rt < 2; rt++)
            #pragma unroll
            for (int j = 0; j < 8; j++){
                sc[rt][j][0]=0.f; sc[rt][j][1]=0.f; sc[rt][j][2]=0.f; sc[rt][j][3]=0.f;
            }
        #pragma unroll
        for (int kc = 0; kc < 8; kc++){
            int c0 = (kc*8 + rg) ^ swzA;
            #pragma unroll
            for (int j = 0; j < 8; j++){
                int rowb = (j*8 + qg)*64;
                unsigned b0 = Ks[rowb +  c0   ];
                unsigned b1 = Ks[rowb + (c0^4)];
                mma_tf32(sc[0][j], qa[0][kc], b0, b1);
                mma_tf32(sc[1][j], qa[1][kc], b0, b1);
            }
        }
        __syncthreads();   // all warps done reading Ks before P overwrites it

        // ---- online softmax per row-tile; write P (overwrites Ks for w<2) ----
        #pragma unroll
        for (int rt = 0; rt < 2; rt++){
            float tm0 = -1e30f, tm1 = -1e30f;
            #pragma unroll
            for (int j = 0; j < 8; j++){
                tm0 = fmaxf(tm0, fmaxf(sc[rt][j][0], sc[rt][j][1]));
                tm1 = fmaxf(tm1, fmaxf(sc[rt][j][2], sc[rt][j][3]));
            }
            tm0 = fmaxf(tm0, __shfl_xor_sync(0xffffffffu, tm0, 1));
            tm0 = fmaxf(tm0, __shfl_xor_sync(0xffffffffu, tm0, 2));
            tm1 = fmaxf(tm1, __shfl_xor_sync(0xffffffffu, tm1, 1));
            tm1 = fmaxf(tm1, __shfl_xor_sync(0xffffffffu, tm1, 2));
            float nm0 = fmaxf(m0[rt], tm0), nm1 = fmaxf(m1[rt], tm1);
            float al0 = __expf(m0[rt] - nm0), al1 = __expf(m1[rt] - nm1);
            m0[rt] = nm0; m1[rt] = nm1;

            float rs0 = 0.f, rs1 = 0.f;
            #pragma unroll
            for (int j = 0; j < 8; j++){
                float p0 = __expf(sc[rt][j][0] - nm0);
                float p1 = __expf(sc[rt][j][1] - nm0);
                float p2 = __expf(sc[rt][j][2] - nm1);
                float p3 = __expf(sc[rt][j][3] - nm1);
                rs0 += p0 + p1;  rs1 += p2 + p3;
                int c = (j*8 + 2*rg) ^ swzA;          // (row&7)==qg for both rows
                *(uint2*)&Pw[(rt*16 + qg  )*64 + c] = make_uint2(f2tf32(p0), f2tf32(p1));
                *(uint2*)&Pw[(rt*16 + qg+8)*64 + c] = make_uint2(f2tf32(p2), f2tf32(p3));
                o[rt][j][0]*=al0; o[rt][j][1]*=al0; o[rt][j][2]*=al1; o[rt][j][3]*=al1;
            }
            rs0 += __shfl_xor_sync(0xffffffffu, rs0, 1);
            rs0 += __shfl_xor_sync(0xffffffffu, rs0, 2);
            rs1 += __shfl_xor_sync(0xffffffffu, rs1, 1);
            rs1 += __shfl_xor_sync(0xffffffffu, rs1, 2);
            l0[rt] = l0[rt]*al0 + rs0;
            l1[rt] = l1[rt]*al1 + rs1;
        }
        __syncwarp();   // P visible within the warp (only own warp reads Pw)

        // ---- O += P V : each V B load feeds BOTH row-tiles ----
        #pragma unroll
        for (int kc = 0; kc < 8; kc++){
            unsigned a0[4], a1[4];
            int c0 = (kc*8 + rg) ^ swzA;
            a0[0] = Pw[( qg   )*64 +  c0   ];
            a0[1] = Pw[( qg+8 )*64 +  c0   ];
            a0[2] = Pw[( qg   )*64 + (c0^4)];
            a0[3] = Pw[( qg+8 )*64 + (c0^4)];
            a1[0] = Pw[(16+qg  )*64 +  c0   ];
            a1[1] = Pw[(16+qg+8)*64 +  c0   ];
            a1[2] = Pw[(16+qg  )*64 + (c0^4)];
            a1[3] = Pw[(16+qg+8)*64 + (c0^4)];
            int vrow = (kc*8 + rg)*64;               // (key&3)==rg -> swizzle == swzB
            #pragma unroll
            for (int j = 0; j < 8; j++){
                int cv = (j*8 + qg) ^ swzB;
                unsigned b0 = Vs[vrow +       cv];
                unsigned b1 = Vs[vrow + 256 + cv];   // key+4 -> +4 rows
                mma_tf32(o[0][j], a0, b0, b1);
                mma_tf32(o[1][j], a1, b0, b1);
            }
        }
        __syncthreads();   // protect Ks(=P)/Vs before next tile's fill
    }

    // ---- epilogue: O /= l, write fp32 ----
    float2* Od = (float2*)(Og + base);
    #pragma unroll
    for (int rt = 0; rt < 2; rt++){
        float inv0 = 1.f / l0[rt], inv1 = 1.f / l1[rt];
        const int row0 = qt*128 + w*32 + rt*16 + qg;
        #pragma unroll
        for (int j = 0; j < 8; j++){
            int d = j*8 + 2*rg;
            Od[( row0   *64 + d) >> 1] = make_float2(o[rt][j][0]*inv0, o[rt][j][1]*inv0);
            Od[((row0+8)*64 + d) >> 1] = make_float2(o[rt][j][2]*inv1, o[rt][j][3]*inv1);
        }
    }
}

extern "C" void kernel_launch(void* const* d_in, const int* in_sizes, int n_in,
                              void* d_out, int out_size){
    const float* Q = (const float*)d_in[0];
    const float* K = (const float*)d_in[1];
    const float* V = (const float*)d_in[2];
    float* O = (float*)d_out;
    dim3 grid(S_LEN/128, BH_NUM);   // q-tile fastest -> same-bh CTAs concurrent -> K/V hit L2
    sdpa_flash_tf32_v4<<<grid, 128>>>(Q, K, V, O);
}

// round 6
// speedup vs baseline: 2.4258x; 1.8758x over previous
#include <cuda_runtime.h>
#include <cuda_fp16.h>
#include <cstdint>

#define BH_NUM 64
#define S_LEN  2048
#define DHEAD  64

__device__ __forceinline__ unsigned packh2(float a, float b){
    __half2 h = __floats2half2_rn(a, b);
    return *reinterpret_cast<unsigned*>(&h);
}

// D = A*B + D,  m16n8k16 f16 inputs, fp32 accumulate
__device__ __forceinline__ void mma_f16(float c[4], const unsigned a[4],
                                        unsigned b0, unsigned b1){
    asm volatile(
        "mma.sync.aligned.m16n8k16.row.col.f32.f16.f16.f32 "
        "{%0,%1,%2,%3}, {%4,%5,%6,%7}, {%8,%9}, {%0,%1,%2,%3};\n"
        : "+f"(c[0]), "+f"(c[1]), "+f"(c[2]), "+f"(c[3])
        : "r"(a[0]), "r"(a[1]), "r"(a[2]), "r"(a[3]), "r"(b0), "r"(b1));
}

// Flash attention v5 (fp16 tensor path):
//  CTA = 128 q-rows, 4 warps x 32 rows (2 x 16-row tiles). KV tile = 64 keys.
//  Ks: K tile [key][d] f16, rows = 32 words (128B), word w stored at w ^ ((key&7)<<2).
//  Vs: V tile TRANSPOSED [dh][key] f16, word w at w ^ (((dh&7)<<2) ^ ((dh>>3)&3)).
//  P lives entirely in registers: f16 C-frag layout == A-frag layout.
__global__ void __launch_bounds__(128, 2)
sdpa_flash_f16_v5(const float* __restrict__ Qg, const float* __restrict__ Kg,
                  const float* __restrict__ Vg, float* __restrict__ Og)
{
    __shared__ unsigned Ks[64*32];   // 8KB: K tile (f16x2 words); Q staging rows 0..63
    __shared__ unsigned Vs[64*32];   // 8KB: V^T tile; Q staging rows 64..127

    const int tid  = threadIdx.x;
    const int w    = tid >> 5;
    const int lane = tid & 31;
    const int qg   = lane >> 2;      // 0..7 (groupID)
    const int rg   = lane & 3;       // 0..3 (threadID-in-group)
    const int swzA = qg << 2;

    const int qt = blockIdx.x;       // 0..15
    const int bh = blockIdx.y;       // 0..63

    const size_t base = (size_t)bh * S_LEN * DHEAD;

    // ---- stage Q tile (128x64 fp32 -> f16, scale 1/8 folded): rows 0..63 -> Ks, 64..127 -> Vs ----
    {
        const float4* Qt4 = (const float4*)(Qg + base + (size_t)qt*128*DHEAD);
        #pragma unroll
        for (int i = 0; i < 16; i++){
            int idx = tid + i*128;        // float4 index 0..2047 (16 per row)
            int row = idx >> 4;
            int c   = idx & 15;
            float4 v = Qt4[idx];
            unsigned* dst = (row < 64) ? Ks : Vs;
            int r = row & 63;
            int d = r*32 + ((2*c) ^ ((r & 7) << 2));   // 2c even, XOR bits[4:2] keep pair adjacent
            uint2 p; p.x = packh2(v.x*0.125f, v.y*0.125f);
                     p.y = packh2(v.z*0.125f, v.w*0.125f);
            *(uint2*)&dst[d] = p;
        }
    }
    __syncthreads();

    // Q fragments in registers: 2 row-tiles x 4 k-chunks(16) x 4 regs (f16x2)
    unsigned qa[2][4][4];
    #pragma unroll
    for (int rt = 0; rt < 2; rt++){
        const int grow = w*32 + rt*16 + qg;          // rows grow, grow+8 in same half
        const unsigned* src = (grow < 64) ? Ks : Vs;
        const int r0 = grow & 63;                    // r0&7 == qg
        #pragma unroll
        for (int kc = 0; kc < 4; kc++){
            qa[rt][kc][0] = src[ r0    *32 + ((8*kc   + rg) ^ swzA)];
            qa[rt][kc][1] = src[(r0+8) *32 + ((8*kc   + rg) ^ swzA)];
            qa[rt][kc][2] = src[ r0    *32 + ((8*kc+4 + rg) ^ swzA)];
            qa[rt][kc][3] = src[(r0+8) *32 + ((8*kc+4 + rg) ^ swzA)];
        }
    }
    __syncthreads();   // staging done; Ks/Vs free

    float o[2][8][4];
    #pragma unroll
    for (int rt = 0; rt < 2; rt++)
        #pragma unroll
        for (int j = 0; j < 8; j++){ o[rt][j][0]=0.f; o[rt][j][1]=0.f; o[rt][j][2]=0.f; o[rt][j][3]=0.f; }
    float m0[2] = {-1e30f,-1e30f}, m1[2] = {-1e30f,-1e30f};
    float l0[2] = {0.f,0.f},       l1[2] = {0.f,0.f};

    const int vdh   = tid & 63;            // V fill: this thread's dh column
    const int vgrp  = tid >> 6;            // 0..1
    const int vs_sw = ((vdh & 7) << 2) ^ ((vdh >> 3) & 3);

    for (int kt = 0; kt < S_LEN/64; kt++){
        // ---- fill K tile [key][d] (f16, swizzled) ----
        const float4* Kt4 = (const float4*)(Kg + base + (size_t)kt*64*DHEAD);
        #pragma unroll
        for (int i = 0; i < 8; i++){
            int idx = tid + i*128;         // 1024 float4s (16 per row)
            int row = idx >> 4;
            int c   = idx & 15;
            float4 kv = Kt4[idx];
            int d = row*32 + ((2*c) ^ ((row & 7) << 2));
            uint2 p; p.x = packh2(kv.x, kv.y); p.y = packh2(kv.z, kv.w);
            *(uint2*)&Ks[d] = p;
        }
        // ---- fill V tile TRANSPOSED [dh][key] (f16, swizzled) ----
        {
            const float* Vt = Vg + base + (size_t)kt*64*DHEAD;
            #pragma unroll
            for (int i = 0; i < 8; i++){
                int k0 = vgrp*4 + i*8;                 // key quad
                float v0 = Vt[(k0+0)*64 + vdh];
                float v1 = Vt[(k0+1)*64 + vdh];
                float v2 = Vt[(k0+2)*64 + vdh];
                float v3 = Vt[(k0+3)*64 + vdh];
                Vs[vdh*32 + (((k0>>1)  ) ^ vs_sw)] = packh2(v0, v1);
                Vs[vdh*32 + (((k0>>1)+1) ^ vs_sw)] = packh2(v2, v3);
            }
        }
        __syncthreads();

        // ---- S = Q K^T : each B load feeds both row-tiles ----
        float sc[2][8][4];
        #pragma unroll
        for (int rt = 0; rt < 2; rt++)
            #pragma unroll
            for (int j = 0; j < 8; j++){ sc[rt][j][0]=0.f; sc[rt][j][1]=0.f; sc[rt][j][2]=0.f; sc[rt][j][3]=0.f; }
        #pragma unroll
        for (int kc = 0; kc < 4; kc++){
            #pragma unroll
            for (int j = 0; j < 8; j++){
                const unsigned* kr = &Ks[(8*j + qg)*32];        // (key&7)==qg -> swizzle == swzA
                unsigned b0 = kr[(8*kc   + rg) ^ swzA];
                unsigned b1 = kr[(8*kc+4 + rg) ^ swzA];
                mma_f16(sc[0][j], qa[0][kc], b0, b1);
                mma_f16(sc[1][j], qa[1][kc], b0, b1);
            }
        }

        // ---- online softmax; P packed straight into A-fragments (registers) ----
        unsigned pa[2][4][4];
        #pragma unroll
        for (int rt = 0; rt < 2; rt++){
            float tm0 = -1e30f, tm1 = -1e30f;
            #pragma unroll
            for (int j = 0; j < 8; j++){
                tm0 = fmaxf(tm0, fmaxf(sc[rt][j][0], sc[rt][j][1]));
                tm1 = fmaxf(tm1, fmaxf(sc[rt][j][2], sc[rt][j][3]));
            }
            tm0 = fmaxf(tm0, __shfl_xor_sync(0xffffffffu, tm0, 1));
            tm0 = fmaxf(tm0, __shfl_xor_sync(0xffffffffu, tm0, 2));
            tm1 = fmaxf(tm1, __shfl_xor_sync(0xffffffffu, tm1, 1));
            tm1 = fmaxf(tm1, __shfl_xor_sync(0xffffffffu, tm1, 2));
            float nm0 = fmaxf(m0[rt], tm0), nm1 = fmaxf(m1[rt], tm1);
            float al0 = __expf(m0[rt] - nm0), al1 = __expf(m1[rt] - nm1);
            m0[rt] = nm0; m1[rt] = nm1;

            float rs0 = 0.f, rs1 = 0.f;
            #pragma unroll
            for (int kc = 0; kc < 4; kc++){
                float e00 = __expf(sc[rt][2*kc  ][0] - nm0);
                float e01 = __expf(sc[rt][2*kc  ][1] - nm0);
                float e02 = __expf(sc[rt][2*kc  ][2] - nm1);
                float e03 = __expf(sc[rt][2*kc  ][3] - nm1);
                float e10 = __expf(sc[rt][2*kc+1][0] - nm0);
                float e11 = __expf(sc[rt][2*kc+1][1] - nm0);
                float e12 = __expf(sc[rt][2*kc+1][2] - nm1);
                float e13 = __expf(sc[rt][2*kc+1][3] - nm1);
                rs0 += e00 + e01 + e10 + e11;
                rs1 += e02 + e03 + e12 + e13;
                // A-frag chunk kc: a0=(row g, k 16kc+2t..), a1=(row g+8), a2=(row g, k+8), a3=(row g+8)
                pa[rt][kc][0] = packh2(e00, e01);
                pa[rt][kc][1] = packh2(e02, e03);
                pa[rt][kc][2] = packh2(e10, e11);
                pa[rt][kc][3] = packh2(e12, e13);
            }
            #pragma unroll
            for (int j = 0; j < 8; j++){
                o[rt][j][0]*=al0; o[rt][j][1]*=al0; o[rt][j][2]*=al1; o[rt][j][3]*=al1;
            }
            rs0 += __shfl_xor_sync(0xffffffffu, rs0, 1);
            rs0 += __shfl_xor_sync(0xffffffffu, rs0, 2);
            rs1 += __shfl_xor_sync(0xffffffffu, rs1, 1);
            rs1 += __shfl_xor_sync(0xffffffffu, rs1, 2);
            l0[rt] = l0[rt]*al0 + rs0;
            l1[rt] = l1[rt]*al1 + rs1;
        }

        // ---- O += P V : V^T in smem, each B load feeds both row-tiles ----
        #pragma unroll
        for (int kc = 0; kc < 4; kc++){
            #pragma unroll
            for (int j = 0; j < 8; j++){
                const unsigned* vr = &Vs[(8*j + qg)*32];
                int vw = swzA ^ (j & 3);               // vs_sw for dh = 8j+qg
                unsigned b0 = vr[(8*kc   + rg) ^ vw];
                unsigned b1 = vr[(8*kc+4 + rg) ^ vw];
                mma_f16(o[0][j], pa[0][kc], b0, b1);
                mma_f16(o[1][j], pa[1][kc], b0, b1);
            }
        }
        __syncthreads();   // protect Ks/Vs before next tile's fill
    }

    // ---- epilogue: O /= l, write fp32 ----
    float2* Od = (float2*)(Og + base);
    #pragma unroll
    for (int rt = 0; rt < 2; rt++){
        float inv0 = 1.f / l0[rt], inv1 = 1.f / l1[rt];
        const int row0 = qt*128 + w*32 + rt*16 + qg;
        #pragma unroll
        for (int j = 0; j < 8; j++){
            int d = j*8 + 2*rg;
            Od[( row0   *64 + d) >> 1] = make_float2(o[rt][j][0]*inv0, o[rt][j][1]*inv0);
            Od[((row0+8)*64 + d) >> 1] = make_float2(o[rt][j][2]*inv1, o[rt][j][3]*inv1);
        }
    }
}

extern "C" void kernel_launch(void* const* d_in, const int* in_sizes, int n_in,
                              void* d_out, int out_size){
    const float* Q = (const float*)d_in[0];
    const float* K = (const float*)d_in[1];
    const float* V = (const float*)d_in[2];
    float* O = (float*)d_out;
    dim3 grid(S_LEN/128, BH_NUM);   // q-tile fastest -> same-bh CTAs share K/V in L2
    sdpa_flash_f16_v5<<<grid, 128>>>(Q, K, V, O);
}